// round 5
// baseline (speedup 1.0000x reference)
#include <cuda_runtime.h>
#include <cuda_bf16.h>
#include <cstdint>
#include <cstddef>

#define NSLAB 2048
// ---------------- SMEM layout (bytes) ----------------
#define W_OFF   0                       // [256][512B] bf16 swizzled = 131072
#define XB_OFF  131072                  // [64][512B] bf16 swizzled  = 32768
#define SC_OFF  163840                  // scores f32 [64][256] swizzled = 65536
#define INV_OFF 229376                  // f32[64]
#define PART_OFF (INV_OFF + 256)        // f32[512]
#define SMEM_BYTES (PART_OFF + 2048 + 16)   // 231,712 B (< 232,448 cap)

__device__ __nv_bfloat16 g_Wbf[256 * 256];

// ---------------- helpers ----------------
__device__ __forceinline__ uint32_t smem_u32(const void* p) {
    uint32_t a;
    asm("{ .reg .u64 t; cvta.to.shared.u64 t, %1; cvt.u32.u64 %0, t; }" : "=r"(a) : "l"(p));
    return a;
}
__device__ __forceinline__ void cp_async16(uint32_t dst, const void* src) {
    asm volatile("cp.async.cg.shared.global [%0], [%1], 16;" :: "r"(dst), "l"(src));
}
__device__ __forceinline__ void cp_commit() { asm volatile("cp.async.commit_group;"); }
template <int N>
__device__ __forceinline__ void cp_wait() { asm volatile("cp.async.wait_group %0;" :: "n"(N) : "memory"); }

__device__ __forceinline__ void ldsm4(uint32_t& r0, uint32_t& r1, uint32_t& r2, uint32_t& r3, uint32_t a) {
    asm volatile("ldmatrix.sync.aligned.m8n8.x4.shared.b16 {%0,%1,%2,%3}, [%4];"
                 : "=r"(r0), "=r"(r1), "=r"(r2), "=r"(r3) : "r"(a));
}
__device__ __forceinline__ void mma_bf16(float& d0, float& d1, float& d2, float& d3,
                                         uint32_t a0, uint32_t a1, uint32_t a2, uint32_t a3,
                                         uint32_t b0, uint32_t b1) {
    asm volatile("mma.sync.aligned.m16n8k16.row.col.f32.bf16.bf16.f32 "
                 "{%0,%1,%2,%3}, {%4,%5,%6,%7}, {%8,%9}, {%0,%1,%2,%3};"
                 : "+f"(d0), "+f"(d1), "+f"(d2), "+f"(d3)
                 : "r"(a0), "r"(a1), "r"(a2), "r"(a3), "r"(b0), "r"(b1));
}
__device__ __forceinline__ void sts128(uint32_t a, uint32_t r0, uint32_t r1, uint32_t r2, uint32_t r3) {
    asm volatile("st.shared.v4.b32 [%0], {%1,%2,%3,%4};" :: "r"(a), "r"(r0), "r"(r1), "r"(r2), "r"(r3));
}
__device__ __forceinline__ float tanh_f(float v) {
    float r; asm("tanh.approx.f32 %0, %1;" : "=f"(r) : "f"(v)); return r;
}
// exp(t) for |t| <= 0.0625: err < 7e-7
__device__ __forceinline__ float exp_small(float t) {
    return fmaf(t, fmaf(t, fmaf(t, 0.16666667f, 0.5f), 1.f), 1.f);
}
__device__ __forceinline__ uint32_t packbf(float a, float b) {
    __nv_bfloat162 v = __floats2bfloat162_rn(a, b);
    return *reinterpret_cast<uint32_t*>(&v);
}

// ---------------- W pre-conversion kernel ----------------
__global__ void conv_w(const float* __restrict__ W) {
    int i = blockIdx.x * 256 + threadIdx.x;
    float4 v = reinterpret_cast<const float4*>(W)[i];
    uint32_t* dst = reinterpret_cast<uint32_t*>(g_Wbf);
    dst[i * 2]     = packbf(v.x, v.y);
    dst[i * 2 + 1] = packbf(v.z, v.w);
}

// ---------------- persistent main kernel ----------------
__global__ __launch_bounds__(512, 1)
void attend_persist(const float* __restrict__ x, const float* __restrict__ b,
                    const float* __restrict__ ctx, float* __restrict__ out)
{
    extern __shared__ char sm[];
    const uint32_t sb = smem_u32(sm);
    float* smf = reinterpret_cast<float*>(sm);
    const int tid = threadIdx.x;
    const int lane = tid & 31, wid = tid >> 5;
    const int warp_m = wid & 3, warp_n = wid >> 2;   // 4 x 4 warp grid, tile m16 x n64
    const int grid = gridDim.x;

    // ---- prologue: W -> SMEM (resident), first x slab -> SMEM ----
    {
        const char* wsrc = reinterpret_cast<const char*>(g_Wbf);
        #pragma unroll
        for (int i = 0; i < 16; ++i) {
            int cid = tid + i * 512;                 // 8192 chunks of 16B
            int o = cid >> 5, ch = cid & 31;
            cp_async16(sb + W_OFF + (uint32_t)(o * 512 + ((ch ^ (o & 7)) << 4)),
                       wsrc + (size_t)o * 512 + ch * 16);
        }
        cp_commit();

        const float4* xg0 = reinterpret_cast<const float4*>(x + (size_t)blockIdx.x * 16384);
        #pragma unroll
        for (int i = 0; i < 4; ++i) {
            int cid = tid + i * 512;                 // 2048 chunks
            int w = cid >> 5, cc = cid & 31;
            float4 v0 = xg0[cid * 2], v1 = xg0[cid * 2 + 1];
            sts128(sb + XB_OFF + (uint32_t)(w * 512 + ((cc ^ (w & 7)) << 4)),
                   packbf(v0.x, v0.y), packbf(v0.z, v0.w),
                   packbf(v1.x, v1.y), packbf(v1.z, v1.w));
        }
        cp_wait<0>();
    }
    __syncthreads();

    // per-lane ldmatrix address components
    const int l7 = lane & 7;
    const int arow = warp_m * 16 + l7 + ((lane >> 3) & 1) * 8;
    const int acb  = (lane >> 4);
    const int brow = l7 + (lane >> 4) * 8;
    const int bch  = ((lane >> 3) & 1);
    const int r = lane & 3, q = lane >> 2;

    float* scf  = smf + SC_OFF / 4;
    float* invp = smf + INV_OFF / 4;
    float* part = smf + PART_OFF / 4;

    for (int s = blockIdx.x; s < NSLAB; s += grid) {
        // ---- prefetch next slab's x into registers (hidden under MMA) ----
        int sp = s + grid; if (sp >= NSLAB) sp = s;
        const float4* xpg = reinterpret_cast<const float4*>(x + (size_t)sp * 16384);
        float4 pf[8];
        #pragma unroll
        for (int i = 0; i < 4; ++i) {
            int cid = tid + i * 512;
            pf[2 * i]     = __ldg(xpg + cid * 2);
            pf[2 * i + 1] = __ldg(xpg + cid * 2 + 1);
        }

        // ---- MMA: y[m16 x n64] over K=256, barrier-free ----
        float c[8][4];
        #pragma unroll
        for (int nj = 0; nj < 8; ++nj)
            #pragma unroll
            for (int e = 0; e < 4; ++e) c[nj][e] = 0.f;

        #pragma unroll
        for (int ks = 0; ks < 16; ++ks) {
            uint32_t a0, a1, a2, a3;
            {
                int cb = ks * 2 + acb;
                ldsm4(a0, a1, a2, a3,
                      sb + XB_OFF + (uint32_t)(arow * 512 + ((cb ^ (arow & 7)) << 4)));
            }
            uint32_t bf[8][2];
            #pragma unroll
            for (int p = 0; p < 4; ++p) {
                int rowb = warp_n * 64 + p * 16 + brow;
                int ch = ks * 2 + bch;
                ldsm4(bf[2*p][0], bf[2*p][1], bf[2*p+1][0], bf[2*p+1][1],
                      sb + W_OFF + (uint32_t)(rowb * 512 + ((ch ^ (rowb & 7)) << 4)));
            }
            #pragma unroll
            for (int nj = 0; nj < 8; ++nj)
                mma_bf16(c[nj][0], c[nj][1], c[nj][2], c[nj][3],
                         a0, a1, a2, a3, bf[nj][0], bf[nj][1]);
        }

        // ---- scores = exp(tanh(y+b)*ctx) -> SMEM ----
        #pragma unroll
        for (int nj = 0; nj < 8; ++nj) {
            int o0 = warp_n * 64 + nj * 8 + 2 * r;
            float2 bo = __ldg(reinterpret_cast<const float2*>(b + o0));
            float2 co = __ldg(reinterpret_cast<const float2*>(ctx + o0));
            int chs = o0 >> 2;
            #pragma unroll
            for (int h = 0; h < 2; ++h) {
                int w = warp_m * 16 + q + h * 8;
                float t0 = tanh_f(c[nj][2*h + 0] + bo.x) * co.x;
                float t1 = tanh_f(c[nj][2*h + 1] + bo.y) * co.y;
                int addr = w * 256 + ((chs ^ (w & 7)) << 2) + (o0 & 3);
                *reinterpret_cast<float2*>(scf + addr) = make_float2(exp_small(t0), exp_small(t1));
            }
        }
        __syncthreads();   // scores visible; all xb reads done

        // ---- store next slab's x (bf16) into SMEM ----
        #pragma unroll
        for (int i = 0; i < 4; ++i) {
            int cid = tid + i * 512;
            int w = cid >> 5, cc = cid & 31;
            sts128(sb + XB_OFF + (uint32_t)(w * 512 + ((cc ^ (w & 7)) << 4)),
                   packbf(pf[2*i].x, pf[2*i].y), packbf(pf[2*i].z, pf[2*i].w),
                   packbf(pf[2*i+1].x, pf[2*i+1].y), packbf(pf[2*i+1].z, pf[2*i+1].w));
        }

        // ---- row sums -> inv (4 rows per warp) ----
        #pragma unroll
        for (int r8 = 0; r8 < 4; ++r8) {
            int row = wid * 4 + r8;
            float sum = 0.f;
            #pragma unroll
            for (int j2 = 0; j2 < 8; ++j2) {
                int col = lane + 32 * j2;
                sum += scf[row * 256 + (((col >> 2) ^ (row & 7)) << 2) + (col & 3)];
            }
            #pragma unroll
            for (int off = 16; off; off >>= 1) sum += __shfl_xor_sync(0xFFFFFFFFu, sum, off);
            if (lane == 0) invp[row] = __fdividef(1.f, sum);
        }
        __syncthreads();   // inv visible

        // ---- output partials: each thread does 32 w's for one col ----
        {
            const int col = tid & 255, half = tid >> 8;
            const float* xgf = x + (size_t)s * 16384 + half * 32 * 256;
            float acc = 0.f;
            #pragma unroll 8
            for (int wl = 0; wl < 32; ++wl) {
                int w = half * 32 + wl;
                float e = scf[w * 256 + (((col >> 2) ^ (w & 7)) << 2) + (col & 3)];
                acc = fmaf(__ldg(xgf + wl * 256 + col), e * invp[w], acc);
            }
            part[tid] = acc;
        }
        __syncthreads();   // partials visible (and score reads complete)

        if (tid < 256)
            out[(size_t)s * 256 + tid] = part[tid] + part[tid + 256];
        // no trailing barrier: next iteration's syncs order all SMEM reuse
    }
}

extern "C" void kernel_launch(void* const* d_in, const int* in_sizes, int n_in,
                              void* d_out, int out_size)
{
    const float* x   = (const float*)d_in[0];
    const float* Wm  = (const float*)d_in[1];
    const float* b   = (const float*)d_in[2];
    const float* ctx = (const float*)d_in[3];
    float* out = (float*)d_out;

    int dev = 0, sms = 148;
    cudaGetDevice(&dev);
    cudaDeviceGetAttribute(&sms, cudaDevAttrMultiProcessorCount, dev);

    cudaFuncSetAttribute(attend_persist, cudaFuncAttributeMaxDynamicSharedMemorySize, SMEM_BYTES);

    conv_w<<<64, 256>>>(Wm);
    attend_persist<<<sms, 512, SMEM_BYTES>>>(x, b, ctx, out);
}

// round 6
// speedup vs baseline: 1.1482x; 1.1482x over previous
#include <cuda_runtime.h>
#include <cuda_bf16.h>
#include <cstdint>
#include <cstddef>

#define NSLAB 2048
// ---------------- SMEM layout (bytes) ----------------
#define W_OFF   0                        // W bf16 [256][512B] swizzled = 131072
#define XB_OFF  131072                   // x bf16 [64][512B] swizzled  = 32768
#define SC_OFF  163840                   // 2 x 32768: (e-1) bf16 [64][512B]
#define RS_OFF  229376                   // f32 [8][64] = 2048
#define INV_OFF 231424                   // f32 [2][64] = 512
#define SMEM_BYTES 231936

__device__ __nv_bfloat16 g_Wbf[256 * 256];

// ---------------- helpers ----------------
__device__ __forceinline__ uint32_t smem_u32(const void* p) {
    uint32_t a;
    asm("{ .reg .u64 t; cvta.to.shared.u64 t, %1; cvt.u32.u64 %0, t; }" : "=r"(a) : "l"(p));
    return a;
}
__device__ __forceinline__ void cp_async16(uint32_t dst, const void* src) {
    asm volatile("cp.async.cg.shared.global [%0], [%1], 16;" :: "r"(dst), "l"(src));
}
__device__ __forceinline__ void cp_commit() { asm volatile("cp.async.commit_group;"); }
template <int N>
__device__ __forceinline__ void cp_wait() { asm volatile("cp.async.wait_group %0;" :: "n"(N) : "memory"); }

__device__ __forceinline__ void ldsm4(uint32_t& r0, uint32_t& r1, uint32_t& r2, uint32_t& r3, uint32_t a) {
    asm volatile("ldmatrix.sync.aligned.m8n8.x4.shared.b16 {%0,%1,%2,%3}, [%4];"
                 : "=r"(r0), "=r"(r1), "=r"(r2), "=r"(r3) : "r"(a));
}
__device__ __forceinline__ void mma_bf16(float& d0, float& d1, float& d2, float& d3,
                                         uint32_t a0, uint32_t a1, uint32_t a2, uint32_t a3,
                                         uint32_t b0, uint32_t b1) {
    asm volatile("mma.sync.aligned.m16n8k16.row.col.f32.bf16.bf16.f32 "
                 "{%0,%1,%2,%3}, {%4,%5,%6,%7}, {%8,%9}, {%0,%1,%2,%3};"
                 : "+f"(d0), "+f"(d1), "+f"(d2), "+f"(d3)
                 : "r"(a0), "r"(a1), "r"(a2), "r"(a3), "r"(b0), "r"(b1));
}
__device__ __forceinline__ void sts128(uint32_t a, uint32_t r0, uint32_t r1, uint32_t r2, uint32_t r3) {
    asm volatile("st.shared.v4.b32 [%0], {%1,%2,%3,%4};" :: "r"(a), "r"(r0), "r"(r1), "r"(r2), "r"(r3));
}
__device__ __forceinline__ void sts32(uint32_t a, uint32_t v) {
    asm volatile("st.shared.b32 [%0], %1;" :: "r"(a), "r"(v));
}
__device__ __forceinline__ uint32_t lds_u16(uint32_t a) {
    uint32_t v; asm volatile("ld.shared.u16 %0, [%1];" : "=r"(v) : "r"(a)); return v;
}
__device__ __forceinline__ float tanh_f(float v) {
    float r; asm("tanh.approx.f32 %0, %1;" : "=f"(r) : "f"(v)); return r;
}
__device__ __forceinline__ uint32_t packbf(float a, float b) {
    __nv_bfloat162 v = __floats2bfloat162_rn(a, b);
    return *reinterpret_cast<uint32_t*>(&v);
}

// ---------------- W pre-conversion ----------------
__global__ void conv_w(const float* __restrict__ W) {
    int i = blockIdx.x * 256 + threadIdx.x;
    float4 v = reinterpret_cast<const float4*>(W)[i];
    uint32_t* dst = reinterpret_cast<uint32_t*>(g_Wbf);
    dst[i * 2]     = packbf(v.x, v.y);
    dst[i * 2 + 1] = packbf(v.z, v.w);
}

// ---------------- persistent pipelined kernel ----------------
__global__ __launch_bounds__(512, 1)
void attend_pipe(const float* __restrict__ x, const float* __restrict__ b,
                 const float* __restrict__ ctx, float* __restrict__ out)
{
    extern __shared__ char sm[];
    const uint32_t sb = smem_u32(sm);
    float* smf = reinterpret_cast<float*>(sm);
    const int tid = threadIdx.x;
    const int lane = tid & 31, wid = tid >> 5;
    const int warp_m = wid & 1, warp_n = wid >> 1;     // 2 x 8 grid, warp tile m32 x n32
    const int q = lane >> 2, r = lane & 3;
    const int l7 = lane & 7;
    const int arow_off = l7 + ((lane >> 3) & 1) * 8;
    const int acb  = lane >> 4;
    const int brow = l7 + (lane >> 4) * 8;
    const int bch  = (lane >> 3) & 1;
    const int grid = gridDim.x;

    // ---- prologue: W resident, first slab x ----
    {
        const char* wsrc = reinterpret_cast<const char*>(g_Wbf);
        #pragma unroll
        for (int i = 0; i < 16; ++i) {
            int cid = tid + i * 512;
            int o = cid >> 5, ch = cid & 31;
            cp_async16(sb + W_OFF + (uint32_t)(o * 512 + ((ch ^ (o & 7)) << 4)),
                       wsrc + (size_t)o * 512 + ch * 16);
        }
        cp_commit();
        const float4* xg0 = reinterpret_cast<const float4*>(x + (size_t)blockIdx.x * 16384);
        #pragma unroll
        for (int i = 0; i < 4; ++i) {
            int cid = tid + i * 512;
            int w = cid >> 5, cc = cid & 31;
            float4 v0 = __ldg(xg0 + cid * 2), v1 = __ldg(xg0 + cid * 2 + 1);
            sts128(sb + XB_OFF + (uint32_t)(w * 512 + ((cc ^ (w & 7)) << 4)),
                   packbf(v0.x, v0.y), packbf(v0.z, v0.w),
                   packbf(v1.x, v1.y), packbf(v1.z, v1.w));
        }
    }
    // bias/ctx fragments (hoisted)
    float2 bo[4], co[4];
    #pragma unroll
    for (int nj = 0; nj < 4; ++nj) {
        int o0 = warp_n * 32 + nj * 8 + 2 * r;
        bo[nj] = __ldg(reinterpret_cast<const float2*>(b + o0));
        co[nj] = __ldg(reinterpret_cast<const float2*>(ctx + o0));
    }
    cp_wait<0>(); __syncthreads();

    const bool outthr = (tid < 256);
    const int col = tid & 255;
    const int cch = col >> 3;
    const int coff = (col & 7) * 2;

    int it = 0, slast = 0, plast = 0;
    for (int s = blockIdx.x; s < NSLAB; s += grid, ++it) {
        const int p = it & 1;
        const bool have = (it > 0);
        const int sprev = s - grid;
        const float* xpv = x + (size_t)(have ? sprev : s) * 16384;

        int snext = s + grid; if (snext >= NSLAB) snext = s;
        const float4* xg = reinterpret_cast<const float4*>(x + (size_t)snext * 16384);
        float4 pf[4];
        #pragma unroll
        for (int i = 0; i < 2; ++i) {
            int cid = tid + i * 512;
            pf[2 * i]     = __ldg(xg + cid * 2);
            pf[2 * i + 1] = __ldg(xg + cid * 2 + 1);
        }

        const uint32_t scprev = sb + SC_OFF + (uint32_t)((p ^ 1) * 32768);
        const float* invprev = smf + INV_OFF / 4 + (p ^ 1) * 64;

        float acc = 0.f;
        float xq[8];
        if (outthr) {
            #pragma unroll
            for (int w = 0; w < 8; ++w) xq[w] = __ldg(xpv + w * 256 + col);
        }

        float c[2][4][4];
        #pragma unroll
        for (int mi = 0; mi < 2; ++mi)
            #pragma unroll
            for (int nj = 0; nj < 4; ++nj)
                #pragma unroll
                for (int e = 0; e < 4; ++e) c[mi][nj][e] = 0.f;

        // ---- MMA over K=256, interleaved with output(prev slab) ----
        #pragma unroll
        for (int ks = 0; ks < 16; ++ks) {
            uint32_t a[2][4];
            #pragma unroll
            for (int mi = 0; mi < 2; ++mi) {
                int row = warp_m * 32 + mi * 16 + arow_off;
                int cb = ks * 2 + acb;
                ldsm4(a[mi][0], a[mi][1], a[mi][2], a[mi][3],
                      sb + XB_OFF + (uint32_t)(row * 512 + ((cb ^ (row & 7)) << 4)));
            }
            uint32_t bfr[4][2];
            #pragma unroll
            for (int pp = 0; pp < 2; ++pp) {
                int rowb = warp_n * 32 + pp * 16 + brow;
                int ch = ks * 2 + bch;
                ldsm4(bfr[2*pp][0], bfr[2*pp][1], bfr[2*pp+1][0], bfr[2*pp+1][1],
                      sb + W_OFF + (uint32_t)(rowb * 512 + ((ch ^ (rowb & 7)) << 4)));
            }
            float ev[4], il[4];
            if (outthr) {
                #pragma unroll
                for (int j = 0; j < 4; ++j) {
                    int w = ks * 4 + j;
                    uint32_t u = lds_u16(scprev + (uint32_t)(w * 512 + ((cch ^ (w & 7)) << 4) + coff));
                    ev[j] = __uint_as_float(u << 16);
                    il[j] = invprev[w];
                }
            }
            #pragma unroll
            for (int mi = 0; mi < 2; ++mi)
                #pragma unroll
                for (int nj = 0; nj < 4; ++nj)
                    mma_bf16(c[mi][nj][0], c[mi][nj][1], c[mi][nj][2], c[mi][nj][3],
                             a[mi][0], a[mi][1], a[mi][2], a[mi][3],
                             bfr[nj][0], bfr[nj][1]);
            if (outthr) {
                #pragma unroll
                for (int j = 0; j < 4; ++j) {
                    int w = ks * 4 + j;
                    acc = fmaf(xq[w & 7], (1.f + ev[j]) * il[j], acc);
                    if (ks < 14) xq[w & 7] = __ldg(xpv + (w + 8) * 256 + col);
                }
            }
        }
        if (outthr && have) out[(size_t)sprev * 256 + col] = acc;
        __syncthreads();                                   // B1

        // ---- W2: second-half x load, score phase, xb refill ----
        float4 pg[4];
        #pragma unroll
        for (int i = 0; i < 2; ++i) {
            int cid = tid + (i + 2) * 512;
            pg[2 * i]     = __ldg(xg + cid * 2);
            pg[2 * i + 1] = __ldg(xg + cid * 2 + 1);
        }
        {
            const uint32_t scur = sb + SC_OFF + (uint32_t)(p * 32768);
            float rloc[4];
            #pragma unroll
            for (int mi = 0; mi < 2; ++mi) {
                #pragma unroll
                for (int h = 0; h < 2; ++h) {
                    int w = warp_m * 32 + mi * 16 + q + 8 * h;
                    float rsum = 0.f;
                    #pragma unroll
                    for (int nj = 0; nj < 4; ++nj) {
                        float t0 = tanh_f(c[mi][nj][2*h + 0] + bo[nj].x) * co[nj].x;
                        float t1 = tanh_f(c[mi][nj][2*h + 1] + bo[nj].y) * co[nj].y;
                        float e0 = t0 * fmaf(t0, fmaf(t0, 0.16666667f, 0.5f), 1.f);  // e-1
                        float e1 = t1 * fmaf(t1, fmaf(t1, 0.16666667f, 0.5f), 1.f);
                        rsum += e0 + e1;
                        sts32(scur + (uint32_t)(w * 512 + (((warp_n * 4 + nj) ^ (w & 7)) << 4) + 4 * r),
                              packbf(e0, e1));
                    }
                    rloc[mi * 2 + h] = rsum;
                }
            }
            #pragma unroll
            for (int k = 0; k < 4; ++k) {
                rloc[k] += __shfl_xor_sync(0xFFFFFFFFu, rloc[k], 1);
                rloc[k] += __shfl_xor_sync(0xFFFFFFFFu, rloc[k], 2);
            }
            if (r == 0) {
                #pragma unroll
                for (int mi = 0; mi < 2; ++mi)
                    #pragma unroll
                    for (int h = 0; h < 2; ++h)
                        smf[RS_OFF / 4 + warp_n * 64 + warp_m * 32 + mi * 16 + q + 8 * h]
                            = rloc[mi * 2 + h];
            }
        }
        #pragma unroll
        for (int i = 0; i < 2; ++i) {
            int cid = tid + i * 512;
            int w = cid >> 5, cc = cid & 31;
            sts128(sb + XB_OFF + (uint32_t)(w * 512 + ((cc ^ (w & 7)) << 4)),
                   packbf(pf[2*i].x, pf[2*i].y), packbf(pf[2*i].z, pf[2*i].w),
                   packbf(pf[2*i+1].x, pf[2*i+1].y), packbf(pf[2*i+1].z, pf[2*i+1].w));
        }
        #pragma unroll
        for (int i = 0; i < 2; ++i) {
            int cid = tid + (i + 2) * 512;
            int w = cid >> 5, cc = cid & 31;
            sts128(sb + XB_OFF + (uint32_t)(w * 512 + ((cc ^ (w & 7)) << 4)),
                   packbf(pg[2*i].x, pg[2*i].y), packbf(pg[2*i].z, pg[2*i].w),
                   packbf(pg[2*i+1].x, pg[2*i+1].y), packbf(pg[2*i+1].z, pg[2*i+1].w));
        }
        __syncthreads();                                   // B2
        if (tid < 64) {
            float ssum = 256.f;
            #pragma unroll
            for (int j = 0; j < 8; ++j) ssum += smf[RS_OFF / 4 + j * 64 + tid];
            smf[INV_OFF / 4 + p * 64 + tid] = __fdividef(1.f, ssum);
        }
        __syncthreads();                                   // B3
        slast = s; plast = p;
    }

    // ---- drain: output for the last slab ----
    if (outthr) {
        const uint32_t sc = sb + SC_OFF + (uint32_t)(plast * 32768);
        const float* invl = smf + INV_OFF / 4 + plast * 64;
        const float* xl = x + (size_t)slast * 16384;
        float acc = 0.f;
        #pragma unroll 8
        for (int w = 0; w < 64; ++w) {
            uint32_t u = lds_u16(sc + (uint32_t)(w * 512 + ((cch ^ (w & 7)) << 4) + coff));
            acc = fmaf(__ldg(xl + w * 256 + col),
                       (1.f + __uint_as_float(u << 16)) * invl[w], acc);
        }
        out[(size_t)slast * 256 + col] = acc;
    }
}

extern "C" void kernel_launch(void* const* d_in, const int* in_sizes, int n_in,
                              void* d_out, int out_size)
{
    const float* x   = (const float*)d_in[0];
    const float* Wm  = (const float*)d_in[1];
    const float* b   = (const float*)d_in[2];
    const float* ctx = (const float*)d_in[3];
    float* out = (float*)d_out;

    int dev = 0, sms = 148;
    cudaGetDevice(&dev);
    cudaDeviceGetAttribute(&sms, cudaDevAttrMultiProcessorCount, dev);

    cudaFuncSetAttribute(attend_pipe, cudaFuncAttributeMaxDynamicSharedMemorySize, SMEM_BYTES);

    conv_w<<<64, 256>>>(Wm);
    attend_pipe<<<sms, 512, SMEM_BYTES>>>(x, b, ctx, out);
}

// round 7
// speedup vs baseline: 1.3927x; 1.2129x over previous
#include <cuda_runtime.h>
#include <cuda_bf16.h>
#include <cstdint>
#include <cstddef>

#define NSLAB 2048
// ---------------- SMEM layout (bytes) ----------------
#define W_OFF  0                    // W bf16 [256][512B] swizzled = 131072
#define XB_OFF 131072               // 2 x 32768 x-slab bf16 swizzled
#define Y_OFF  196608               // y bf16 [64][512B] swizzled = 32768 (part[8][256] f32 overlays)
#define SMEM_BYTES 229376

__device__ __nv_bfloat16 g_Wbf[256 * 256];

// ---------------- helpers ----------------
__device__ __forceinline__ uint32_t smem_u32(const void* p) {
    uint32_t a;
    asm("{ .reg .u64 t; cvta.to.shared.u64 t, %1; cvt.u32.u64 %0, t; }" : "=r"(a) : "l"(p));
    return a;
}
__device__ __forceinline__ void cp_async16(uint32_t dst, const void* src) {
    asm volatile("cp.async.cg.shared.global [%0], [%1], 16;" :: "r"(dst), "l"(src));
}
__device__ __forceinline__ void cp_commit() { asm volatile("cp.async.commit_group;"); }
template <int N>
__device__ __forceinline__ void cp_wait() { asm volatile("cp.async.wait_group %0;" :: "n"(N) : "memory"); }

__device__ __forceinline__ void ldsm4(uint32_t& r0, uint32_t& r1, uint32_t& r2, uint32_t& r3, uint32_t a) {
    asm volatile("ldmatrix.sync.aligned.m8n8.x4.shared.b16 {%0,%1,%2,%3}, [%4];"
                 : "=r"(r0), "=r"(r1), "=r"(r2), "=r"(r3) : "r"(a));
}
__device__ __forceinline__ void mma_bf16(float& d0, float& d1, float& d2, float& d3,
                                         uint32_t a0, uint32_t a1, uint32_t a2, uint32_t a3,
                                         uint32_t b0, uint32_t b1) {
    asm volatile("mma.sync.aligned.m16n8k16.row.col.f32.bf16.bf16.f32 "
                 "{%0,%1,%2,%3}, {%4,%5,%6,%7}, {%8,%9}, {%0,%1,%2,%3};"
                 : "+f"(d0), "+f"(d1), "+f"(d2), "+f"(d3)
                 : "r"(a0), "r"(a1), "r"(a2), "r"(a3), "r"(b0), "r"(b1));
}
__device__ __forceinline__ void sts128(uint32_t a, uint32_t r0, uint32_t r1, uint32_t r2, uint32_t r3) {
    asm volatile("st.shared.v4.b32 [%0], {%1,%2,%3,%4};" :: "r"(a), "r"(r0), "r"(r1), "r"(r2), "r"(r3));
}
__device__ __forceinline__ void sts32(uint32_t a, uint32_t v) {
    asm volatile("st.shared.b32 [%0], %1;" :: "r"(a), "r"(v));
}
__device__ __forceinline__ void sts64f(uint32_t a, float v0, float v1) {
    asm volatile("st.shared.v2.f32 [%0], {%1,%2};" :: "r"(a), "f"(v0), "f"(v1));
}
__device__ __forceinline__ uint32_t lds_u32(uint32_t a) {
    uint32_t v; asm volatile("ld.shared.b32 %0, [%1];" : "=r"(v) : "r"(a)); return v;
}
__device__ __forceinline__ float tanh_f(float v) {
    float r; asm("tanh.approx.f32 %0, %1;" : "=f"(r) : "f"(v)); return r;
}
__device__ __forceinline__ uint32_t packbf(float a, float b) {
    __nv_bfloat162 v = __floats2bfloat162_rn(a, b);
    return *reinterpret_cast<uint32_t*>(&v);
}
__device__ __forceinline__ void bar_sync(int id, int cnt) {
    asm volatile("bar.sync %0, %1;" :: "r"(id), "r"(cnt) : "memory");
}
__device__ __forceinline__ void bar_arrive(int id, int cnt) {
    asm volatile("bar.arrive %0, %1;" :: "r"(id), "r"(cnt) : "memory");
}
__device__ __forceinline__ void membar_cta() {
    asm volatile("membar.cta;" ::: "memory");
}

// ---------------- W pre-conversion ----------------
__global__ void conv_w(const float* __restrict__ W) {
    int i = blockIdx.x * 256 + threadIdx.x;
    float4 v = reinterpret_cast<const float4*>(W)[i];
    uint32_t* dst = reinterpret_cast<uint32_t*>(g_Wbf);
    dst[i * 2]     = packbf(v.x, v.y);
    dst[i * 2 + 1] = packbf(v.z, v.w);
}

// ---------------- warp-specialized persistent kernel ----------------
__global__ __launch_bounds__(512, 1)
void attend_ws(const float* __restrict__ x, const float* __restrict__ b,
               const float* __restrict__ ctx, float* __restrict__ out)
{
    extern __shared__ char sm[];
    const uint32_t sb = smem_u32(sm);
    float* smf = reinterpret_cast<float*>(sm);
    const int tid = threadIdx.x;
    const int lane = tid & 31, wid = tid >> 5;
    const int grid = gridDim.x, bid = blockIdx.x;
    const int nit = (NSLAB - 1 - bid) / grid + 1;

    // ---- prologue: W resident + xb[0], xb[1] ----
    {
        const char* wsrc = reinterpret_cast<const char*>(g_Wbf);
        #pragma unroll
        for (int i = 0; i < 16; ++i) {
            int cid = tid + i * 512;
            int o = cid >> 5, ch = cid & 31;
            cp_async16(sb + W_OFF + (uint32_t)(o * 512 + ((ch ^ (o & 7)) << 4)),
                       wsrc + (size_t)o * 512 + ch * 16);
        }
        cp_commit();
        #pragma unroll
        for (int buf = 0; buf < 2; ++buf) {
            const float4* xg = reinterpret_cast<const float4*>(
                x + (size_t)(bid + buf * grid) * 16384);
            #pragma unroll
            for (int i = 0; i < 4; ++i) {
                int cid = tid + i * 512;
                int w = cid >> 5, cc = cid & 31;
                float4 v0 = __ldg(xg + cid * 2), v1 = __ldg(xg + cid * 2 + 1);
                sts128(sb + XB_OFF + (uint32_t)(buf * 32768 + w * 512 + ((cc ^ (w & 7)) << 4)),
                       packbf(v0.x, v0.y), packbf(v0.z, v0.w),
                       packbf(v1.x, v1.y), packbf(v1.z, v1.w));
            }
        }
        cp_wait<0>();
    }
    __syncthreads();

    if (wid < 8) {
        // ================= MMA warps: m64 x n32 each =================
        const int wn = wid;
        const int l7 = lane & 7;
        const int arow_off = l7 + ((lane >> 3) & 1) * 8;
        const int acb  = lane >> 4;
        const int brow = l7 + (lane >> 4) * 8;
        const int bch  = (lane >> 3) & 1;
        const int q = lane >> 2, r = lane & 3;

        for (int it = 0; it < nit; ++it) {
            const uint32_t xbb = sb + XB_OFF + (uint32_t)((it & 1) * 32768);
            float c[4][4][4];
            #pragma unroll
            for (int mt = 0; mt < 4; ++mt)
                #pragma unroll
                for (int nt = 0; nt < 4; ++nt)
                    #pragma unroll
                    for (int e = 0; e < 4; ++e) c[mt][nt][e] = 0.f;

            #pragma unroll
            for (int ks = 0; ks < 16; ++ks) {
                uint32_t a[4][4];
                #pragma unroll
                for (int mt = 0; mt < 4; ++mt) {
                    int row = mt * 16 + arow_off;
                    int cb = ks * 2 + acb;
                    ldsm4(a[mt][0], a[mt][1], a[mt][2], a[mt][3],
                          xbb + (uint32_t)(row * 512 + ((cb ^ (row & 7)) << 4)));
                }
                uint32_t bf2[4][2];
                #pragma unroll
                for (int pp = 0; pp < 2; ++pp) {
                    int rowb = wn * 32 + pp * 16 + brow;
                    int ch = ks * 2 + bch;
                    ldsm4(bf2[2*pp][0], bf2[2*pp][1], bf2[2*pp+1][0], bf2[2*pp+1][1],
                          sb + W_OFF + (uint32_t)(rowb * 512 + ((ch ^ (rowb & 7)) << 4)));
                }
                #pragma unroll
                for (int mt = 0; mt < 4; ++mt)
                    #pragma unroll
                    for (int nt = 0; nt < 4; ++nt)
                        mma_bf16(c[mt][nt][0], c[mt][nt][1], c[mt][nt][2], c[mt][nt][3],
                                 a[mt][0], a[mt][1], a[mt][2], a[mt][3],
                                 bf2[nt][0], bf2[nt][1]);
            }

            bar_sync(2, 512);        // ybuf free (epi of prev slab done)
            #pragma unroll
            for (int mt = 0; mt < 4; ++mt) {
                #pragma unroll
                for (int nt = 0; nt < 4; ++nt) {
                    int ch = wn * 4 + nt;
                    int r0 = mt * 16 + q, r1 = r0 + 8;
                    sts32(sb + Y_OFF + (uint32_t)(r0 * 512 + ((ch ^ (r0 & 7)) << 4) + 4 * r),
                          packbf(c[mt][nt][0], c[mt][nt][1]));
                    sts32(sb + Y_OFF + (uint32_t)(r1 * 512 + ((ch ^ (r1 & 7)) << 4) + 4 * r),
                          packbf(c[mt][nt][2], c[mt][nt][3]));
                }
            }
            membar_cta();
            bar_arrive(1, 512);      // y ready
        }
    } else {
        // ================= EPI warps =================
        const int ewid = wid - 8;            // 0..7: rows ewid*8 .. ewid*8+7
        const int l = lane;
        const int et = tid - 256;            // 0..255
        float2 bfr[4], cfr[4];
        #pragma unroll
        for (int j = 0; j < 4; ++j) {
            bfr[j] = __ldg(reinterpret_cast<const float2*>(b + 2 * l + 64 * j));
            cfr[j] = __ldg(reinterpret_cast<const float2*>(ctx + 2 * l + 64 * j));
        }
        bar_arrive(2, 512);                  // initial: ybuf free

        for (int it = 0; it < nit; ++it) {
            const int s = bid + it * grid;
            bar_sync(1, 512);                // y(s) ready
            const float* xs = x + (size_t)s * 16384;
            float p[8];
            #pragma unroll
            for (int k = 0; k < 8; ++k) p[k] = 0.f;

            #pragma unroll
            for (int rg = 0; rg < 2; ++rg) {
                float ee[4][8], iv[4];
                #pragma unroll
                for (int i = 0; i < 4; ++i) {
                    int row = ewid * 8 + rg * 4 + i;
                    uint32_t rb = sb + Y_OFF + (uint32_t)(row * 512);
                    float rsum = 0.f;
                    #pragma unroll
                    for (int j = 0; j < 4; ++j) {
                        int ch = (l >> 2) + 8 * j;
                        uint32_t u = lds_u32(rb + (uint32_t)(((ch ^ (row & 7)) << 4) + (l & 3) * 4));
                        float y0 = __uint_as_float(u << 16);
                        float y1 = __uint_as_float(u & 0xFFFF0000u);
                        float t0 = tanh_f(y0 + bfr[j].x) * cfr[j].x;
                        float t1 = tanh_f(y1 + bfr[j].y) * cfr[j].y;
                        float e0 = fmaf(t0, fmaf(t0, fmaf(t0, 0.16666667f, 0.5f), 1.f), 1.f);
                        float e1 = fmaf(t1, fmaf(t1, fmaf(t1, 0.16666667f, 0.5f), 1.f), 1.f);
                        ee[i][2*j] = e0; ee[i][2*j+1] = e1;
                        rsum += e0 + e1;
                    }
                    #pragma unroll
                    for (int off = 16; off; off >>= 1)
                        rsum += __shfl_xor_sync(0xFFFFFFFFu, rsum, off);
                    iv[i] = __fdividef(1.f, rsum);
                }
                #pragma unroll
                for (int i = 0; i < 4; ++i) {
                    int row = ewid * 8 + rg * 4 + i;
                    #pragma unroll
                    for (int j = 0; j < 4; ++j) {
                        float2 xv = __ldg(reinterpret_cast<const float2*>(
                                          xs + row * 256 + 2 * l + 64 * j));
                        p[2*j]   = fmaf(ee[i][2*j]   * iv[i], xv.x, p[2*j]);
                        p[2*j+1] = fmaf(ee[i][2*j+1] * iv[i], xv.y, p[2*j+1]);
                    }
                }
            }
            bar_sync(3, 256);                // all epi warps done reading ybuf
            #pragma unroll
            for (int j = 0; j < 4; ++j)
                sts64f(sb + Y_OFF + (uint32_t)(ewid * 1024 + (2 * l + 64 * j) * 4),
                       p[2*j], p[2*j+1]);
            bar_sync(3, 256);                // partials visible
            {
                float o = 0.f;
                #pragma unroll
                for (int we = 0; we < 8; ++we)
                    o += smf[Y_OFF / 4 + we * 256 + et];
                out[(size_t)s * 256 + et] = o;
            }
            // refill xb[it&1] with slab s + 2*grid
            int s2 = s + 2 * grid;
            if (s2 < NSLAB) {
                const float4* xg = reinterpret_cast<const float4*>(x + (size_t)s2 * 16384);
                #pragma unroll
                for (int i = 0; i < 8; ++i) {
                    int cid = et + i * 256;
                    int w = cid >> 5, cc = cid & 31;
                    float4 v0 = __ldg(xg + cid * 2), v1 = __ldg(xg + cid * 2 + 1);
                    sts128(sb + XB_OFF + (uint32_t)((it & 1) * 32768 + w * 512 + ((cc ^ (w & 7)) << 4)),
                           packbf(v0.x, v0.y), packbf(v0.z, v0.w),
                           packbf(v1.x, v1.y), packbf(v1.z, v1.w));
                }
            }
            membar_cta();
            bar_arrive(2, 512);              // ybuf free + xb refilled
        }
    }
}

extern "C" void kernel_launch(void* const* d_in, const int* in_sizes, int n_in,
                              void* d_out, int out_size)
{
    const float* x   = (const float*)d_in[0];
    const float* Wm  = (const float*)d_in[1];
    const float* b   = (const float*)d_in[2];
    const float* ctx = (const float*)d_in[3];
    float* out = (float*)d_out;

    int dev = 0, sms = 148;
    cudaGetDevice(&dev);
    cudaDeviceGetAttribute(&sms, cudaDevAttrMultiProcessorCount, dev);

    cudaFuncSetAttribute(attend_ws, cudaFuncAttributeMaxDynamicSharedMemorySize, SMEM_BYTES);

    conv_w<<<64, 256>>>(Wm);
    attend_ws<<<sms, 512, SMEM_BYTES>>>(x, b, ctx, out);
}